// round 1
// baseline (speedup 1.0000x reference)
#include <cuda_runtime.h>
#include <cuda_bf16.h>

#define NODES_MAX 50000
#define FEATS 128
#define KNBR 20

// Scratch for aggregated neighborhood features G = sum(e * V[idx]) / denom
__device__ float g_G[NODES_MAX * FEATS];

// ---------------- packed f32x2 helpers (sm_100+) ----------------
__device__ __forceinline__ unsigned long long ffma2(unsigned long long a,
                                                    unsigned long long b,
                                                    unsigned long long c) {
    unsigned long long d;
    asm("fma.rn.f32x2 %0, %1, %2, %3;" : "=l"(d) : "l"(a), "l"(b), "l"(c));
    return d;
}
__device__ __forceinline__ unsigned long long pack2(float x) {
    unsigned long long d;
    unsigned int u = __float_as_uint(x);
    asm("mov.b64 %0, {%1, %1};" : "=l"(d) : "r"(u));
    return d;
}
__device__ __forceinline__ float2 unpack2(unsigned long long v) {
    float2 r;
    asm("mov.b64 {%0, %1}, %2;" : "=f"(r.x), "=f"(r.y) : "l"(v));
    return r;
}

// ---------------- Kernel 1: gather-aggregate ----------------
// One warp per node. G[i][:] = (1/denom_i) * sum_j e_ij * V[idx_ij][:]
__global__ void agg_kernel(const float4* __restrict__ verts,
                           const int* __restrict__ nh_idx,
                           const int* __restrict__ int_idx,
                           const float* __restrict__ nh_e,
                           const float* __restrict__ int_e,
                           int n) {
    int node = blockIdx.x * (blockDim.x >> 5) + (threadIdx.x >> 5);
    if (node >= n) return;
    int lane = threadIdx.x & 31;

    int   iA = -1, iB = -1;
    float eA = 0.f, eB = 0.f;
    if (lane < KNBR) {
        int base = node * KNBR + lane;
        iA = nh_idx[base];
        eA = nh_e[base];
        iB = int_idx[base];
        eB = int_e[base];
    }
    // number of valid interface neighbors (nh are always valid)
    int validB = __popc(__ballot_sync(0xffffffffu, (lane < KNBR) && (iB >= 0)));

    float4 acc = make_float4(0.f, 0.f, 0.f, 0.f);

#pragma unroll
    for (int j = 0; j < KNBR; j++) {
        int   idx = __shfl_sync(0xffffffffu, iA, j);
        float e   = __shfl_sync(0xffffffffu, eA, j);
        float4 v  = __ldg(&verts[idx * (FEATS / 4) + lane]);
        acc.x = fmaf(e, v.x, acc.x);
        acc.y = fmaf(e, v.y, acc.y);
        acc.z = fmaf(e, v.z, acc.z);
        acc.w = fmaf(e, v.w, acc.w);
    }
#pragma unroll
    for (int j = 0; j < KNBR; j++) {
        int idx = __shfl_sync(0xffffffffu, iB, j);
        if (idx >= 0) {  // warp-uniform
            float e  = __shfl_sync(0xffffffffu, eB, j);
            float4 v = __ldg(&verts[idx * (FEATS / 4) + lane]);
            acc.x = fmaf(e, v.x, acc.x);
            acc.y = fmaf(e, v.y, acc.y);
            acc.z = fmaf(e, v.z, acc.z);
            acc.w = fmaf(e, v.w, acc.w);
        }
    }
    float inv = 1.0f / (float)(KNBR + validB);
    acc.x *= inv; acc.y *= inv; acc.z *= inv; acc.w *= inv;
    *reinterpret_cast<float4*>(&g_G[node * FEATS + lane * 4]) = acc;
}

// ---------------- Kernel 2: fused dual GEMM + bias + relu ----------------
// out[M,128] = relu( X[M,128] @ Wvc + G[M,128] @ Wvn + bv )
// BM=128, BN=128, BK=16, Ktot=256 (first 128 from X/Wvc, next 128 from G/Wvn).
// 256 threads, each computes 8 rows x 8 cols using packed f32x2 FMA.
__global__ __launch_bounds__(256, 2)
void gemm_kernel(const float* __restrict__ X,
                 const float* __restrict__ Wvc,
                 const float* __restrict__ Wvn,
                 const float* __restrict__ bv,
                 float* __restrict__ out,
                 int n) {
    __shared__ float As[16][132];   // transposed: As[k][row], +4 pad keeps 16B align
    __shared__ float Bs[16][128];   // Bs[k][col]

    const int tid = threadIdx.x;
    const int block_row = blockIdx.x * 128;
    const int ty = tid >> 4;   // 0..15 -> rows ty*8 .. ty*8+7
    const int tx = tid & 15;   // 0..15 -> cols tx*4..+3 and 64+tx*4..+3

    unsigned long long acc[8][4];  // [col][rowpair]; each ull = 2 fp32 rows
#pragma unroll
    for (int c = 0; c < 8; c++)
#pragma unroll
        for (int rp = 0; rp < 4; rp++) acc[c][rp] = 0ull;

    for (int kt = 0; kt < 16; kt++) {
        const float* Asrc;
        const float* Bsrc;
        if (kt < 8) {
            Asrc = X + kt * 16;
            Bsrc = Wvc + kt * 16 * 128;
        } else {
            Asrc = g_G + (kt - 8) * 16;
            Bsrc = Wvn + (kt - 8) * 16 * 128;
        }
        // Load A tile (128 rows x 16 k), store transposed.
#pragma unroll
        for (int i = 0; i < 2; i++) {
            int f4 = tid * 2 + i;          // 0..511
            int r  = f4 >> 2;              // 0..127
            int kq = (f4 & 3) << 2;        // 0,4,8,12
            int grow = block_row + r;
            if (grow >= n) grow = n - 1;   // clamp; stores are predicated later
            float4 v = *reinterpret_cast<const float4*>(Asrc + (long long)grow * FEATS + kq);
            As[kq + 0][r] = v.x;
            As[kq + 1][r] = v.y;
            As[kq + 2][r] = v.z;
            As[kq + 3][r] = v.w;
        }
        // Load B tile (16 k x 128 cols)
#pragma unroll
        for (int i = 0; i < 2; i++) {
            int f4 = tid * 2 + i;          // 0..511
            int kk = f4 >> 5;              // 0..15
            int nn = (f4 & 31) << 2;       // 0..124
            *reinterpret_cast<float4*>(&Bs[kk][nn]) =
                *reinterpret_cast<const float4*>(Bsrc + kk * 128 + nn);
        }
        __syncthreads();

#pragma unroll
        for (int k = 0; k < 16; k++) {
            ulonglong2 a01 = *reinterpret_cast<const ulonglong2*>(&As[k][ty * 8]);
            ulonglong2 a23 = *reinterpret_cast<const ulonglong2*>(&As[k][ty * 8 + 4]);
            unsigned long long ap[4] = {a01.x, a01.y, a23.x, a23.y};
            float4 b0 = *reinterpret_cast<const float4*>(&Bs[k][tx * 4]);
            float4 b1 = *reinterpret_cast<const float4*>(&Bs[k][tx * 4 + 64]);
            unsigned long long bb[8];
            bb[0] = pack2(b0.x); bb[1] = pack2(b0.y);
            bb[2] = pack2(b0.z); bb[3] = pack2(b0.w);
            bb[4] = pack2(b1.x); bb[5] = pack2(b1.y);
            bb[6] = pack2(b1.z); bb[7] = pack2(b1.w);
#pragma unroll
            for (int c = 0; c < 8; c++)
#pragma unroll
                for (int rp = 0; rp < 4; rp++)
                    acc[c][rp] = ffma2(ap[rp], bb[c], acc[c][rp]);
        }
        __syncthreads();
    }

    // Epilogue: + bias, relu, store
    float4 bva = *reinterpret_cast<const float4*>(bv + tx * 4);
    float4 bvb = *reinterpret_cast<const float4*>(bv + 64 + tx * 4);

#pragma unroll
    for (int rp = 0; rp < 4; rp++) {
        float2 c0 = unpack2(acc[0][rp]);
        float2 c1 = unpack2(acc[1][rp]);
        float2 c2 = unpack2(acc[2][rp]);
        float2 c3 = unpack2(acc[3][rp]);
        float2 c4 = unpack2(acc[4][rp]);
        float2 c5 = unpack2(acc[5][rp]);
        float2 c6 = unpack2(acc[6][rp]);
        float2 c7 = unpack2(acc[7][rp]);

        int row0 = block_row + ty * 8 + rp * 2;
        int row1 = row0 + 1;

        if (row0 < n) {
            float4 oA, oB;
            oA.x = fmaxf(c0.x + bva.x, 0.f);
            oA.y = fmaxf(c1.x + bva.y, 0.f);
            oA.z = fmaxf(c2.x + bva.z, 0.f);
            oA.w = fmaxf(c3.x + bva.w, 0.f);
            oB.x = fmaxf(c4.x + bvb.x, 0.f);
            oB.y = fmaxf(c5.x + bvb.y, 0.f);
            oB.z = fmaxf(c6.x + bvb.z, 0.f);
            oB.w = fmaxf(c7.x + bvb.w, 0.f);
            *reinterpret_cast<float4*>(out + (long long)row0 * FEATS + tx * 4) = oA;
            *reinterpret_cast<float4*>(out + (long long)row0 * FEATS + 64 + tx * 4) = oB;
        }
        if (row1 < n) {
            float4 oA, oB;
            oA.x = fmaxf(c0.y + bva.x, 0.f);
            oA.y = fmaxf(c1.y + bva.y, 0.f);
            oA.z = fmaxf(c2.y + bva.z, 0.f);
            oA.w = fmaxf(c3.y + bva.w, 0.f);
            oB.x = fmaxf(c4.y + bvb.x, 0.f);
            oB.y = fmaxf(c5.y + bvb.y, 0.f);
            oB.z = fmaxf(c6.y + bvb.z, 0.f);
            oB.w = fmaxf(c7.y + bvb.w, 0.f);
            *reinterpret_cast<float4*>(out + (long long)row1 * FEATS + tx * 4) = oA;
            *reinterpret_cast<float4*>(out + (long long)row1 * FEATS + 64 + tx * 4) = oB;
        }
    }
}

extern "C" void kernel_launch(void* const* d_in, const int* in_sizes, int n_in,
                              void* d_out, int out_size) {
    const float* vertices = (const float*)d_in[0];
    const int*   nh_idx   = (const int*)d_in[1];
    const int*   int_idx  = (const int*)d_in[2];
    const float* nh_e     = (const float*)d_in[3];
    const float* int_e    = (const float*)d_in[4];
    const float* Wvc      = (const float*)d_in[5];
    const float* Wvn      = (const float*)d_in[6];
    const float* bv       = (const float*)d_in[7];
    float* out = (float*)d_out;

    int n = in_sizes[0] / FEATS;  // 50000

    int warps_per_block = 256 / 32;
    int agg_blocks = (n + warps_per_block - 1) / warps_per_block;
    agg_kernel<<<agg_blocks, 256>>>(
        (const float4*)vertices, nh_idx, int_idx, nh_e, int_e, n);

    int gemm_blocks = (n + 127) / 128;
    gemm_kernel<<<gemm_blocks, 256>>>(vertices, Wvc, Wvn, bv, out, n);
}

// round 4
// speedup vs baseline: 1.2920x; 1.2920x over previous
#include <cuda_runtime.h>
#include <cuda_bf16.h>

#define NODES_MAX 50000
#define FEATS 128
#define KNBR 20

// Scratch for aggregated neighborhood features G = sum(e * V[idx]) / denom
__device__ float g_G[NODES_MAX * FEATS];

// =================== helpers ===================
__device__ __forceinline__ unsigned int smem_u32(const void* p) {
    unsigned int a;
    asm("{ .reg .u64 t; cvta.to.shared.u64 t, %1; cvt.u32.u64 %0, t; }"
        : "=r"(a) : "l"(p));
    return a;
}

__device__ __forceinline__ void ldsm4(unsigned int r[4], unsigned int addr) {
    asm volatile("ldmatrix.sync.aligned.m8n8.x4.shared.b16 {%0,%1,%2,%3}, [%4];"
                 : "=r"(r[0]), "=r"(r[1]), "=r"(r[2]), "=r"(r[3])
                 : "r"(addr));
}

__device__ __forceinline__ void mma16816(float c[4], const unsigned int a[4],
                                         unsigned int b0, unsigned int b1) {
    asm volatile(
        "mma.sync.aligned.m16n8k16.row.col.f32.bf16.bf16.f32 "
        "{%0,%1,%2,%3}, {%4,%5,%6,%7}, {%8,%9}, {%0,%1,%2,%3};"
        : "+f"(c[0]), "+f"(c[1]), "+f"(c[2]), "+f"(c[3])
        : "r"(a[0]), "r"(a[1]), "r"(a[2]), "r"(a[3]), "r"(b0), "r"(b1));
}

__device__ __forceinline__ unsigned int sw128(unsigned int b) {
    return b ^ ((b >> 3) & 0x70);
}
// byte offset (pre-swizzle) of element (row, k) in a [128 x 128] bf16 K-major
// tile stored as two 64-k planes of 16KB, 128B rows
__device__ __forceinline__ unsigned int tile_off(int row, int k) {
    return ((unsigned)(k >> 6) << 14) + ((unsigned)row << 7) + ((unsigned)(k & 63) << 1);
}

__device__ __forceinline__ unsigned long long pack4bf(float a, float b, float c, float d) {
    __nv_bfloat162 lo = __floats2bfloat162_rn(a, b);
    __nv_bfloat162 hi = __floats2bfloat162_rn(c, d);
    unsigned int ulo = *reinterpret_cast<unsigned int*>(&lo);
    unsigned int uhi = *reinterpret_cast<unsigned int*>(&hi);
    unsigned long long u;
    asm("mov.b64 %0, {%1, %2};" : "=l"(u) : "r"(ulo), "r"(uhi));
    return u;
}

// =================== smem layout (dynamic) ===================
// [1024]    B tiles: Wc_h, Wc_l, Wn_h, Wn_l  (each 32KB, [n][k] K-major SW128)
// [132096]  A_h tile (32KB), [164864] A_l tile (32KB)
#define SM_B 1024u
#define SM_AH 132096u
#define SM_AL 164864u
#define SM_TOTAL 197632

// ---------------- Kernel 1: gather-aggregate ----------------
__global__ void agg_kernel(const float4* __restrict__ verts,
                           const int* __restrict__ nh_idx,
                           const int* __restrict__ int_idx,
                           const float* __restrict__ nh_e,
                           const float* __restrict__ int_e,
                           int n) {
    int node = blockIdx.x * (blockDim.x >> 5) + (threadIdx.x >> 5);
    if (node >= n) return;
    int lane = threadIdx.x & 31;

    int   iA = -1, iB = -1;
    float eA = 0.f, eB = 0.f;
    if (lane < KNBR) {
        int base = node * KNBR + lane;
        iA = nh_idx[base];
        eA = nh_e[base];
        iB = int_idx[base];
        eB = int_e[base];
    }
    int validB = __popc(__ballot_sync(0xffffffffu, (lane < KNBR) && (iB >= 0)));

    float4 acc = make_float4(0.f, 0.f, 0.f, 0.f);
#pragma unroll
    for (int j = 0; j < KNBR; j++) {
        int   idx = __shfl_sync(0xffffffffu, iA, j);
        float e   = __shfl_sync(0xffffffffu, eA, j);
        float4 v  = __ldg(&verts[idx * (FEATS / 4) + lane]);
        acc.x = fmaf(e, v.x, acc.x);
        acc.y = fmaf(e, v.y, acc.y);
        acc.z = fmaf(e, v.z, acc.z);
        acc.w = fmaf(e, v.w, acc.w);
    }
#pragma unroll
    for (int j = 0; j < KNBR; j++) {
        int idx = __shfl_sync(0xffffffffu, iB, j);
        if (idx >= 0) {
            float e  = __shfl_sync(0xffffffffu, eB, j);
            float4 v = __ldg(&verts[idx * (FEATS / 4) + lane]);
            acc.x = fmaf(e, v.x, acc.x);
            acc.y = fmaf(e, v.y, acc.y);
            acc.z = fmaf(e, v.z, acc.z);
            acc.w = fmaf(e, v.w, acc.w);
        }
    }
    float inv = 1.0f / (float)(KNBR + validB);
    acc.x *= inv; acc.y *= inv; acc.z *= inv; acc.w *= inv;
    *reinterpret_cast<float4*>(&g_G[node * FEATS + lane * 4]) = acc;
}

// ---------------- Kernel 2: HMMA bf16 3-term dual GEMM ----------------
// out = relu( [V|G] @ [Wvc;Wvn] + bv ), fp32-accurate via hi/lo bf16 split.
__global__ __launch_bounds__(512, 1)
void gemm_tc(const float* __restrict__ X,
             const float* __restrict__ Wvc,
             const float* __restrict__ Wvn,
             const float* __restrict__ bv,
             float* __restrict__ out,
             int n, int ntiles) {
    extern __shared__ char smem[];
    unsigned int sb = smem_u32(smem);
    const int tid = threadIdx.x;
    const int wid = tid >> 5;
    const int lane = tid & 31;

    // ---- convert both weight matrices once per CTA, transposed to [n][k] ----
    for (int m = 0; m < 2; m++) {
        const float* W = m ? Wvn : Wvc;
        char* bh = smem + SM_B + m * 65536;
        char* bl = bh + 32768;
        for (int idx = tid; idx < 4096; idx += 512) {
            int k  = idx >> 5;
            int n4 = (idx & 31) << 2;
            float4 w = *reinterpret_cast<const float4*>(W + k * FEATS + n4);
            float wv[4] = {w.x, w.y, w.z, w.w};
#pragma unroll
            for (int i = 0; i < 4; i++) {
                __nv_bfloat16 h = __float2bfloat16(wv[i]);
                float hf = __bfloat162float(h);
                __nv_bfloat16 l = __float2bfloat16(wv[i] - hf);
                unsigned int off = sw128(tile_off(n4 + i, k));
                *reinterpret_cast<__nv_bfloat16*>(bh + off) = h;
                *reinterpret_cast<__nv_bfloat16*>(bl + off) = l;
            }
        }
    }
    __syncthreads();

    // ---- per-warp ldmatrix address precompute (pure-XOR SW128 form) ----
    const int wm = wid & 3;        // row-block of warp (32 rows)
    const int wn = wid >> 2;       // col-block of warp (32 cols)
    const int mIdx = lane >> 3;    // ldmatrix matrix index 0..3
    const int r8 = lane & 7;

    // A: matrix m -> rowblk = m&1 (+8 rows), kblk = m>>1 (+8 k)
    const int rowA = wm * 32 + ((mIdx & 1) << 3) + r8;
    const unsigned int prowA =
        ((unsigned)rowA << 7) ^ (((unsigned)rowA & 7) << 4) ^ (((unsigned)mIdx >> 1) << 4);
    // B: matrix m -> nblk = m>>1 (+8 n), kblk = m&1 (+8 k)
    const int rowB = wn * 32 + ((mIdx >> 1) << 3) + r8;
    const unsigned int prowB =
        ((unsigned)rowB << 7) ^ (((unsigned)rowB & 7) << 4) ^ (((unsigned)mIdx & 1) << 4);

    const unsigned int aH = sb + SM_AH;
    const unsigned int aL = sb + SM_AL;

    // bias fragments
    float2 biasj[4];
#pragma unroll
    for (int j = 0; j < 4; j++) {
        int c = wn * 32 + j * 8 + ((lane & 3) << 1);
        biasj[j].x = __ldg(bv + c);
        biasj[j].y = __ldg(bv + c + 1);
    }

    for (int tile = blockIdx.x; tile < ntiles; tile += gridDim.x) {
        float acc[2][4][4];
#pragma unroll
        for (int i = 0; i < 2; i++)
#pragma unroll
            for (int j = 0; j < 4; j++)
#pragma unroll
                for (int q = 0; q < 4; q++) acc[i][j][q] = 0.f;

#pragma unroll
        for (int s = 0; s < 2; s++) {
            const float* A = s ? (const float*)g_G : X;
            __syncthreads();  // previous phase's reads of A smem are done
            // load + split A tile [128 rows x 128 k]
            for (int idx = tid; idx < 4096; idx += 512) {
                int r  = idx >> 5;
                int k4 = (idx & 31) << 2;
                int gr = tile * 128 + r;
                if (gr >= n) gr = n - 1;
                float4 v = *reinterpret_cast<const float4*>(A + (long long)gr * FEATS + k4);
                float av[4] = {v.x, v.y, v.z, v.w};
                float hf[4], lf[4];
#pragma unroll
                for (int i = 0; i < 4; i++) {
                    __nv_bfloat16 h = __float2bfloat16(av[i]);
                    hf[i] = __bfloat162float(h);
                    lf[i] = av[i] - hf[i];
                }
                unsigned int off = sw128(tile_off(r, k4));
                *reinterpret_cast<unsigned long long*>(smem + SM_AH + off) =
                    pack4bf(hf[0], hf[1], hf[2], hf[3]);
                *reinterpret_cast<unsigned long long*>(smem + SM_AL + off) =
                    pack4bf(lf[0], lf[1], lf[2], lf[3]);
            }
            __syncthreads();

            const unsigned int bHs = sb + SM_B + (unsigned)s * 65536u;
            const unsigned int bLs = bHs + 32768u;

#pragma unroll
            for (int ks = 0; ks < 8; ks++) {
                const unsigned int Kc =
                    (((unsigned)ks >> 2) << 14) | (((unsigned)ks & 3) << 5);
                unsigned int ah[2][4], al[2][4], bh[2][4], bl[2][4];
                ldsm4(ah[0], aH + (prowA ^ Kc));
                ldsm4(ah[1], aH + (prowA ^ 0x800u ^ Kc));
                ldsm4(al[0], aL + (prowA ^ Kc));
                ldsm4(al[1], aL + (prowA ^ 0x800u ^ Kc));
                ldsm4(bh[0], bHs + (prowB ^ Kc));
                ldsm4(bh[1], bHs + (prowB ^ 0x800u ^ Kc));
                ldsm4(bl[0], bLs + (prowB ^ Kc));
                ldsm4(bl[1], bLs + (prowB ^ 0x800u ^ Kc));
#pragma unroll
                for (int i = 0; i < 2; i++) {
#pragma unroll
                    for (int j = 0; j < 4; j++) {
                        unsigned int b0h = bh[j >> 1][(j & 1) * 2];
                        unsigned int b1h = bh[j >> 1][(j & 1) * 2 + 1];
                        unsigned int b0l = bl[j >> 1][(j & 1) * 2];
                        unsigned int b1l = bl[j >> 1][(j & 1) * 2 + 1];
                        mma16816(acc[i][j], ah[i], b0h, b1h);  // Ah*Bh
                        mma16816(acc[i][j], ah[i], b0l, b1l);  // Ah*Bl
                        mma16816(acc[i][j], al[i], b0h, b1h);  // Al*Bh
                    }
                }
            }
        }

        // ---- epilogue: bias + relu + store from registers ----
        int row_base = tile * 128 + wm * 32 + (lane >> 2);
#pragma unroll
        for (int i = 0; i < 2; i++) {
            int r0 = row_base + i * 16;
            int r1 = r0 + 8;
#pragma unroll
            for (int j = 0; j < 4; j++) {
                int col = wn * 32 + j * 8 + ((lane & 3) << 1);
                if (r0 < n) {
                    float2 o;
                    o.x = fmaxf(acc[i][j][0] + biasj[j].x, 0.f);
                    o.y = fmaxf(acc[i][j][1] + biasj[j].y, 0.f);
                    *reinterpret_cast<float2*>(out + (long long)r0 * FEATS + col) = o;
                }
                if (r1 < n) {
                    float2 o;
                    o.x = fmaxf(acc[i][j][2] + biasj[j].x, 0.f);
                    o.y = fmaxf(acc[i][j][3] + biasj[j].y, 0.f);
                    *reinterpret_cast<float2*>(out + (long long)r1 * FEATS + col) = o;
                }
            }
        }
    }
}

extern "C" void kernel_launch(void* const* d_in, const int* in_sizes, int n_in,
                              void* d_out, int out_size) {
    const float* vertices = (const float*)d_in[0];
    const int*   nh_idx   = (const int*)d_in[1];
    const int*   int_idx  = (const int*)d_in[2];
    const float* nh_e     = (const float*)d_in[3];
    const float* int_e    = (const float*)d_in[4];
    const float* Wvc      = (const float*)d_in[5];
    const float* Wvn      = (const float*)d_in[6];
    const float* bv       = (const float*)d_in[7];
    float* out = (float*)d_out;

    int n = in_sizes[0] / FEATS;  // 50000

    int warps_per_block = 256 / 32;
    int agg_blocks = (n + warps_per_block - 1) / warps_per_block;
    agg_kernel<<<agg_blocks, 256>>>(
        (const float4*)vertices, nh_idx, int_idx, nh_e, int_e, n);

    int ntiles = (n + 127) / 128;
    int grid = ntiles < 148 ? ntiles : 148;
    cudaFuncSetAttribute(gemm_tc, cudaFuncAttributeMaxDynamicSharedMemorySize, SM_TOTAL);
    gemm_tc<<<grid, 512, SM_TOTAL>>>(vertices, Wvc, Wvn, bv, out, n, ntiles);
}

// round 5
// speedup vs baseline: 1.3186x; 1.0206x over previous
#include <cuda_runtime.h>
#include <cuda_bf16.h>

#define NODES_MAX 50000
#define FEATS 128
#define KNBR 20

// Pre-converted bf16 hi/lo planes of V and G, row-major [N][128]
__device__ __nv_bfloat16 g_Vh[NODES_MAX * FEATS];
__device__ __nv_bfloat16 g_Vl[NODES_MAX * FEATS];
__device__ __nv_bfloat16 g_Gh[NODES_MAX * FEATS];
__device__ __nv_bfloat16 g_Gl[NODES_MAX * FEATS];

// =================== helpers ===================
__device__ __forceinline__ unsigned int smem_u32(const void* p) {
    unsigned int a;
    asm("{ .reg .u64 t; cvta.to.shared.u64 t, %1; cvt.u32.u64 %0, t; }"
        : "=r"(a) : "l"(p));
    return a;
}

__device__ __forceinline__ void ldsm4(unsigned int r[4], unsigned int addr) {
    asm volatile("ldmatrix.sync.aligned.m8n8.x4.shared.b16 {%0,%1,%2,%3}, [%4];"
                 : "=r"(r[0]), "=r"(r[1]), "=r"(r[2]), "=r"(r[3])
                 : "r"(addr));
}

__device__ __forceinline__ void mma16816(float c[4], const unsigned int a[4],
                                         unsigned int b0, unsigned int b1) {
    asm volatile(
        "mma.sync.aligned.m16n8k16.row.col.f32.bf16.bf16.f32 "
        "{%0,%1,%2,%3}, {%4,%5,%6,%7}, {%8,%9}, {%0,%1,%2,%3};"
        : "+f"(c[0]), "+f"(c[1]), "+f"(c[2]), "+f"(c[3])
        : "r"(a[0]), "r"(a[1]), "r"(a[2]), "r"(a[3]), "r"(b0), "r"(b1));
}

__device__ __forceinline__ void cp16(unsigned int dst, const void* src) {
    asm volatile("cp.async.cg.shared.global [%0], [%1], 16;"
                 :: "r"(dst), "l"(__cvta_generic_to_global(src)) : "memory");
}
#define CP_COMMIT() asm volatile("cp.async.commit_group;" ::: "memory")
#define CP_WAIT1()  asm volatile("cp.async.wait_group 1;" ::: "memory")

__device__ __forceinline__ unsigned int sw128(unsigned int b) {
    return b ^ ((b >> 3) & 0x70);
}
// [128 x 128] bf16 K-major tile = two 64-k planes of 16KB, 128B rows
__device__ __forceinline__ unsigned int tile_off(int row, int k) {
    return ((unsigned)(k >> 6) << 14) + ((unsigned)row << 7) + ((unsigned)(k & 63) << 1);
}

__device__ __forceinline__ unsigned int pack2bf_hi(float a, float b) {
    __nv_bfloat162 p = __floats2bfloat162_rn(a, b);
    return *reinterpret_cast<unsigned int*>(&p);
}

// =================== smem layout (dynamic) ===================
// [0]       weights: Wc_h, Wc_l, Wn_h, Wn_l (each 32KB, [n][k] K-major SW128)
// [131072]  A chunk double buffer: 2 x {hi 16KB, lo 16KB}
#define SM_B 0u
#define SM_A 131072u
#define SM_TOTAL 196608

// ---------------- Kernel 1: gather-aggregate + bf16 pre-conversion ----------------
__global__ void agg_kernel(const float4* __restrict__ verts,
                           const int* __restrict__ nh_idx,
                           const int* __restrict__ int_idx,
                           const float* __restrict__ nh_e,
                           const float* __restrict__ int_e,
                           int n) {
    int node = blockIdx.x * (blockDim.x >> 5) + (threadIdx.x >> 5);
    if (node >= n) return;
    int lane = threadIdx.x & 31;

    int   iA = -1, iB = -1;
    float eA = 0.f, eB = 0.f;
    if (lane < KNBR) {
        int base = node * KNBR + lane;
        iA = nh_idx[base];
        eA = nh_e[base];
        iB = int_idx[base];
        eB = int_e[base];
    }
    int validB = __popc(__ballot_sync(0xffffffffu, (lane < KNBR) && (iB >= 0)));

    float4 acc = make_float4(0.f, 0.f, 0.f, 0.f);
#pragma unroll
    for (int j = 0; j < KNBR; j++) {
        int   idx = __shfl_sync(0xffffffffu, iA, j);
        float e   = __shfl_sync(0xffffffffu, eA, j);
        float4 v  = __ldg(&verts[idx * (FEATS / 4) + lane]);
        acc.x = fmaf(e, v.x, acc.x);
        acc.y = fmaf(e, v.y, acc.y);
        acc.z = fmaf(e, v.z, acc.z);
        acc.w = fmaf(e, v.w, acc.w);
    }
#pragma unroll
    for (int j = 0; j < KNBR; j++) {
        int idx = __shfl_sync(0xffffffffu, iB, j);
        if (idx >= 0) {
            float e  = __shfl_sync(0xffffffffu, eB, j);
            float4 v = __ldg(&verts[idx * (FEATS / 4) + lane]);
            acc.x = fmaf(e, v.x, acc.x);
            acc.y = fmaf(e, v.y, acc.y);
            acc.z = fmaf(e, v.z, acc.z);
            acc.w = fmaf(e, v.w, acc.w);
        }
    }
    float inv = 1.0f / (float)(KNBR + validB);
    acc.x *= inv; acc.y *= inv; acc.z *= inv; acc.w *= inv;

    // split G into bf16 hi/lo and store
    {
        float gv[4] = {acc.x, acc.y, acc.z, acc.w};
        float hf[4];
#pragma unroll
        for (int i = 0; i < 4; i++)
            hf[i] = __bfloat162float(__float2bfloat16(gv[i]));
        uint2 hi = make_uint2(pack2bf_hi(hf[0], hf[1]), pack2bf_hi(hf[2], hf[3]));
        uint2 lo = make_uint2(pack2bf_hi(gv[0] - hf[0], gv[1] - hf[1]),
                              pack2bf_hi(gv[2] - hf[2], gv[3] - hf[3]));
        reinterpret_cast<uint2*>(g_Gh)[node * 32 + lane] = hi;
        reinterpret_cast<uint2*>(g_Gl)[node * 32 + lane] = lo;
    }
    // convert own V row (hot in cache from gathers)
    {
        float4 v = __ldg(&verts[node * (FEATS / 4) + lane]);
        float vv[4] = {v.x, v.y, v.z, v.w};
        float hf[4];
#pragma unroll
        for (int i = 0; i < 4; i++)
            hf[i] = __bfloat162float(__float2bfloat16(vv[i]));
        uint2 hi = make_uint2(pack2bf_hi(hf[0], hf[1]), pack2bf_hi(hf[2], hf[3]));
        uint2 lo = make_uint2(pack2bf_hi(vv[0] - hf[0], vv[1] - hf[1]),
                              pack2bf_hi(vv[2] - hf[2], vv[3] - hf[3]));
        reinterpret_cast<uint2*>(g_Vh)[node * 32 + lane] = hi;
        reinterpret_cast<uint2*>(g_Vl)[node * 32 + lane] = lo;
    }
}

// ---------------- Kernel 2: pipelined HMMA 3-term dual GEMM ----------------
__global__ __launch_bounds__(512, 1)
void gemm_tc(const float* __restrict__ Wvc,
             const float* __restrict__ Wvn,
             const float* __restrict__ bv,
             float* __restrict__ out,
             int n, int ntiles) {
    extern __shared__ char smem[];
    unsigned int sb = smem_u32(smem);
    const int tid = threadIdx.x;
    const int wid = tid >> 5;
    const int lane = tid & 31;

    // chunk loader: 32KB (hi+lo planes of one 64-k half) via cp.async
    auto load_chunk = [&](int buf, int tile, int s, int h) {
        const __nv_bfloat16* srcH = s ? g_Gh : g_Vh;
        const __nv_bfloat16* srcL = s ? g_Gl : g_Vl;
        unsigned int dstBase = sb + SM_A + (unsigned)buf * 32768u;
#pragma unroll
        for (int i = 0; i < 2; i++) {
            int idx = i * 512 + tid;       // 0..1023
            int row = idx >> 3;
            int u   = idx & 7;             // 16B unit within 128B row-half
            int gr = tile * 128 + row;
            if (gr >= n) gr = n - 1;
            unsigned int off = sw128((unsigned)(row * 128 + u * 16));
            long long sOff = (long long)gr * 256 + h * 128 + u * 16;
            cp16(dstBase + off, (const char*)srcH + sOff);
            cp16(dstBase + 16384u + off, (const char*)srcL + sOff);
        }
    };

    // ---- kick off first chunk load, then convert weights while it flies ----
    if (blockIdx.x < (unsigned)ntiles) load_chunk(0, blockIdx.x, 0, 0);
    CP_COMMIT();

    for (int m = 0; m < 2; m++) {
        const float* W = m ? Wvn : Wvc;
        char* bh = smem + SM_B + m * 65536;
        char* bl = bh + 32768;
        for (int idx = tid; idx < 4096; idx += 512) {
            int k  = idx >> 5;
            int n4 = (idx & 31) << 2;
            float4 w = *reinterpret_cast<const float4*>(W + k * FEATS + n4);
            float wv[4] = {w.x, w.y, w.z, w.w};
#pragma unroll
            for (int i = 0; i < 4; i++) {
                __nv_bfloat16 h = __float2bfloat16(wv[i]);
                float hf = __bfloat162float(h);
                __nv_bfloat16 l = __float2bfloat16(wv[i] - hf);
                unsigned int off = sw128(tile_off(n4 + i, k));
                *reinterpret_cast<__nv_bfloat16*>(bh + off) = h;
                *reinterpret_cast<__nv_bfloat16*>(bl + off) = l;
            }
        }
    }

    // ---- per-warp ldmatrix addresses (pure-XOR SW128 form, within-plane) ----
    const int wm = wid & 3;        // 32-row block
    const int wn = wid >> 2;       // 32-col block
    const int mIdx = lane >> 3;
    const int r8 = lane & 7;

    const int rowA = wm * 32 + ((mIdx & 1) << 3) + r8;
    const unsigned int prowA =
        ((unsigned)rowA << 7) ^ (((unsigned)rowA & 7) << 4) ^ (((unsigned)mIdx >> 1) << 4);
    const int rowB = wn * 32 + ((mIdx >> 1) << 3) + r8;
    const unsigned int prowB =
        ((unsigned)rowB << 7) ^ (((unsigned)rowB & 7) << 4) ^ (((unsigned)mIdx & 1) << 4);

    float2 biasj[4];
#pragma unroll
    for (int j = 0; j < 4; j++) {
        int c = wn * 32 + j * 8 + ((lane & 3) << 1);
        biasj[j].x = __ldg(bv + c);
        biasj[j].y = __ldg(bv + c + 1);
    }

    for (int tile = blockIdx.x; tile < ntiles; tile += gridDim.x) {
        float acc[2][4][4];
#pragma unroll
        for (int i = 0; i < 2; i++)
#pragma unroll
            for (int j = 0; j < 4; j++)
#pragma unroll
                for (int q = 0; q < 4; q++) acc[i][j][q] = 0.f;

        int buf = 0;
#pragma unroll
        for (int c = 0; c < 4; c++) {
            const int s = c >> 1, h = c & 1;
            __syncthreads();  // prior MMA readers of buf^1 are done
            if (c < 3) {
                load_chunk(buf ^ 1, tile, (c + 1) >> 1, (c + 1) & 1);
            } else {
                int nt = tile + gridDim.x;
                if (nt < ntiles) load_chunk(buf ^ 1, nt, 0, 0);
            }
            CP_COMMIT();
            CP_WAIT1();       // current chunk's data has landed (per-thread)
            __syncthreads();  // ... and is visible CTA-wide

            const unsigned int aHp = sb + SM_A + (unsigned)buf * 32768u;
            const unsigned int aLp = aHp + 16384u;
            const unsigned int bHp = sb + SM_B + (unsigned)s * 65536u + (unsigned)h * 16384u;
            const unsigned int bLp = bHp + 32768u;

#pragma unroll
            for (int ks = 0; ks < 4; ks++) {
                const unsigned int Kc = (unsigned)ks << 5;
                unsigned int ah[2][4], al[2][4], bh[2][4], bl[2][4];
                ldsm4(ah[0], aHp + (prowA ^ Kc));
                ldsm4(ah[1], aHp + (prowA ^ 0x800u ^ Kc));
                ldsm4(al[0], aLp + (prowA ^ Kc));
                ldsm4(al[1], aLp + (prowA ^ 0x800u ^ Kc));
                ldsm4(bh[0], bHp + (prowB ^ Kc));
                ldsm4(bh[1], bHp + (prowB ^ 0x800u ^ Kc));
                ldsm4(bl[0], bLp + (prowB ^ Kc));
                ldsm4(bl[1], bLp + (prowB ^ 0x800u ^ Kc));
#pragma unroll
                for (int i = 0; i < 2; i++) {
#pragma unroll
                    for (int j = 0; j < 4; j++) {
                        unsigned int b0h = bh[j >> 1][(j & 1) * 2];
                        unsigned int b1h = bh[j >> 1][(j & 1) * 2 + 1];
                        unsigned int b0l = bl[j >> 1][(j & 1) * 2];
                        unsigned int b1l = bl[j >> 1][(j & 1) * 2 + 1];
                        mma16816(acc[i][j], ah[i], b0h, b1h);  // Ah*Bh
                        mma16816(acc[i][j], ah[i], b0l, b1l);  // Ah*Bl
                        mma16816(acc[i][j], al[i], b0h, b1h);  // Al*Bh
                    }
                }
            }
            buf ^= 1;
        }

        // ---- epilogue (overlaps next tile's prefetch) ----
        int row_base = tile * 128 + wm * 32 + (lane >> 2);
#pragma unroll
        for (int i = 0; i < 2; i++) {
            int r0 = row_base + i * 16;
            int r1 = r0 + 8;
#pragma unroll
            for (int j = 0; j < 4; j++) {
                int col = wn * 32 + j * 8 + ((lane & 3) << 1);
                if (r0 < n) {
                    float2 o;
                    o.x = fmaxf(acc[i][j][0] + biasj[j].x, 0.f);
                    o.y = fmaxf(acc[i][j][1] + biasj[j].y, 0.f);
                    *reinterpret_cast<float2*>(out + (long long)r0 * FEATS + col) = o;
                }
                if (r1 < n) {
                    float2 o;
                    o.x = fmaxf(acc[i][j][2] + biasj[j].x, 0.f);
                    o.y = fmaxf(acc[i][j][3] + biasj[j].y, 0.f);
                    *reinterpret_cast<float2*>(out + (long long)r1 * FEATS + col) = o;
                }
            }
        }
    }
}

extern "C" void kernel_launch(void* const* d_in, const int* in_sizes, int n_in,
                              void* d_out, int out_size) {
    const float* vertices = (const float*)d_in[0];
    const int*   nh_idx   = (const int*)d_in[1];
    const int*   int_idx  = (const int*)d_in[2];
    const float* nh_e     = (const float*)d_in[3];
    const float* int_e    = (const float*)d_in[4];
    const float* Wvc      = (const float*)d_in[5];
    const float* Wvn      = (const float*)d_in[6];
    const float* bv       = (const float*)d_in[7];
    float* out = (float*)d_out;

    int n = in_sizes[0] / FEATS;  // 50000

    int warps_per_block = 256 / 32;
    int agg_blocks = (n + warps_per_block - 1) / warps_per_block;
    agg_kernel<<<agg_blocks, 256>>>(
        (const float4*)vertices, nh_idx, int_idx, nh_e, int_e, n);

    int ntiles = (n + 127) / 128;
    int grid = ntiles < 148 ? ntiles : 148;
    cudaFuncSetAttribute(gemm_tc, cudaFuncAttributeMaxDynamicSharedMemorySize, SM_TOTAL);
    gemm_tc<<<grid, 512, SM_TOTAL>>>(Wvc, Wvn, bv, out, n, ntiles);
}